// round 16
// baseline (speedup 1.0000x reference)
#include <cuda_runtime.h>
#include <math.h>

#define B_  64
#define T_  2048
#define IN_ 128
#define H_  256

typedef unsigned long long ull;

// ---------------- scratch ----------------
__device__ float g_h1[(size_t)B_ * T_ * H_];    // layer-0 hidden states
__device__ float g_h2last[(size_t)B_ * H_];     // h2[:, T-1, :]

// ---------------- packed fp32x2 helpers ----------------
__device__ __forceinline__ void fma2(ull &d, ull a, ull b) {
    asm("fma.rn.f32x2 %0, %1, %2, %0;" : "+l"(d) : "l"(a), "l"(b));
}
__device__ __forceinline__ ull splat2(float x) {
    ull r; asm("mov.b64 %0, {%1, %1};" : "=l"(r) : "f"(x)); return r;
}
__device__ __forceinline__ ull pack2(float a, float b) {
    ull r; asm("mov.b64 %0, {%1, %2};" : "=l"(r) : "r"(__float_as_uint(a)), "r"(__float_as_uint(b)));
    return r;
}
__device__ __forceinline__ float lo2(ull v) { return __uint_as_float((unsigned)(v & 0xffffffffULL)); }
__device__ __forceinline__ float hi2(ull v) { return __uint_as_float((unsigned)(v >> 32)); }

__device__ __forceinline__ float tanh_fast(float s) {
    s = fminf(fmaxf(s, -15.f), 15.f);
    float e; asm("ex2.approx.f32 %0, %1;" : "=f"(e) : "f"(s * 2.885390082f));
    float r; asm("rcp.approx.f32 %0, %1;" : "=f"(r) : "f"(e + 1.f));
    return fmaf(-2.f, r, 1.f);
}

// ---------------- cluster / mbarrier helpers (rec3/rec7-proven) ----------------
__device__ __forceinline__ unsigned su32(const void* p) {
    return (unsigned)__cvta_generic_to_shared(p);
}
__device__ __forceinline__ unsigned cta_rank() {
    unsigned r; asm("mov.u32 %0, %%cluster_ctarank;" : "=r"(r)); return r;
}
__device__ __forceinline__ unsigned mapa_u32(unsigned addr, unsigned rank) {
    unsigned r; asm("mapa.shared::cluster.u32 %0, %1, %2;" : "=r"(r) : "r"(addr), "r"(rank));
    return r;
}
__device__ __forceinline__ void mbar_init(unsigned addr, unsigned cnt) {
    asm volatile("mbarrier.init.shared.b64 [%0], %1;" :: "r"(addr), "r"(cnt) : "memory");
}
__device__ __forceinline__ void mbar_expect_tx(unsigned addr, unsigned bytes) {
    asm volatile("mbarrier.arrive.expect_tx.shared.b64 _, [%0], %1;" :: "r"(addr), "r"(bytes) : "memory");
}
__device__ __forceinline__ void mbar_wait_cluster(unsigned addr, unsigned parity) {
    asm volatile(
        "{\n\t.reg .pred P;\n\t"
        "WL_%=:\n\t"
        "mbarrier.try_wait.parity.acquire.cluster.shared::cta.b64 P, [%0], %1, 0x989680;\n\t"
        "@P bra.uni WD_%=;\n\t"
        "bra.uni WL_%=;\n\t"
        "WD_%=:\n\t}"
        :: "r"(addr), "r"(parity) : "memory");
}
__device__ __forceinline__ void st_async_b64(unsigned raddr, ull v, unsigned rmbar) {
    asm volatile(
        "st.async.shared::cluster.mbarrier::complete_tx::bytes.b64 [%0], %1, [%2];"
        :: "r"(raddr), "l"(v), "r"(rmbar) : "memory");
}
__device__ __forceinline__ void cluster_sync_() {
    asm volatile("barrier.cluster.arrive.aligned;" ::: "memory");
    asm volatile("barrier.cluster.wait.aligned;" ::: "memory");
}

// =====================================================================================
// Fused recurrence: rec7 protocol + in-kernel input projection (replaces the GEMMs).
// KIN=128: layer 0, xin = x.  KIN=256: layer 1, xin = h1 (global, complete).
// Thread (og=tid>>3, kc=tid&7): 4 outputs o0..o0+3, h k-chunk of 32, x k-chunk of CH.
// Per step: [off-chain] compute x-projection partials from staged x[t] (smem) into
// accumulators; prefetch x[t+1]; [chain] mbar wait -> h-matvec (accumulate) -> shfl
// tree -> epi lanes: tanh(bias + total) -> STS + 2x st.async.b64 -> stage x[t+1].
// Protocol identical to rec7: slot t&1, parity (t>>1)&1, 512B tx, drain at end.
// Smem: [mbar 2ull][h_sm 2x288][xstg 2x8xXP][Wx 8 x (CH x 132 + 4)].
// =====================================================================================
template<int KIN, bool STORE_ALL>
__global__ void __cluster_dims__(2, 1, 1) __launch_bounds__(256, 1)
rnn_recF(const float* __restrict__ xin, const float* __restrict__ Wih,
         const float* __restrict__ bih, const float* __restrict__ bhh,
         const float* __restrict__ Whh, float* __restrict__ hout)
{
    constexpr int CH = KIN / 8;            // x k per kc lane
    constexpr int XP = CH + 4;             // padded x chunk stride
    constexpr int WC = CH * 132 + 4;       // Wx per-kc-chunk stride (floats)
    extern __shared__ float smf[];
    ull*   mbar = (ull*)smf;               // [2]
    float* h_sm = smf + 4;                 // [2][288]
    float* xstg = h_sm + 576;              // [2][8*XP]
    float* Wx   = xstg + 2 * 8 * XP;       // [8][WC]

    const int tid = threadIdx.x;
    const unsigned rank = cta_rank();
    const unsigned peer = rank ^ 1u;
    const int b = blockIdx.x >> 1;
    const int kc = tid & 7, og = tid >> 3;
    const int o0 = og * 4;
    const int o0g = (int)rank * 128 + o0;
    const int kbase = (kc < 4) ? ((int)rank * 128 + kc * 32)
                               : ((int)peer * 128 + (kc - 4) * 32);

    // ---- Whh weights in regs (4 outputs x 32 k) ----
    ull wq[4][16];
#pragma unroll
    for (int i = 0; i < 4; ++i) {
        const ulonglong2* src = (const ulonglong2*)(Whh + (size_t)(o0g + i) * H_ + kbase);
#pragma unroll
        for (int j = 0; j < 8; ++j) { ulonglong2 v = src[j]; wq[i][2 * j] = v.x; wq[i][2 * j + 1] = v.y; }
    }

    // ---- Wih into smem: Wx[kc][k][out] ----
    for (int idx = tid; idx < KIN * 128; idx += 256) {
        int k = idx >> 7, o = idx & 127;
        Wx[(k / CH) * WC + (k % CH) * 132 + o] =
            Wih[(size_t)((int)rank * 128 + o) * KIN + k];
    }
    if (tid == 0) { mbar_init(su32(&mbar[0]), 1); mbar_init(su32(&mbar[1]), 1); }
    for (int i = tid; i < 2 * 288; i += 256) h_sm[i] = 0.f;
    // stage x[0]
    if (tid < KIN / 4) {
        float4 v = __ldg((const float4*)(xin + (size_t)b * T_ * KIN + 4 * tid));
        *(float4*)&xstg[(4 * tid / CH) * XP + (4 * tid % CH)] = v;
    }
    __syncthreads();
    cluster_sync_();

    const unsigned my_mbar   = su32(&mbar[0]);
    const unsigned peer_mbar = mapa_u32(my_mbar, peer);
    const unsigned peer_h    = mapa_u32(su32(h_sm), peer);

    const bool epi = (kc == 0);
    const int chunk = og >> 3, coff = (og & 7) * 4;
    float4 bv = make_float4(0.f, 0.f, 0.f, 0.f);
    if (epi) {
        bv.x = bih[o0g] + bhh[o0g];         bv.y = bih[o0g + 1] + bhh[o0g + 1];
        bv.z = bih[o0g + 2] + bhh[o0g + 2]; bv.w = bih[o0g + 3] + bhh[o0g + 3];
    }
    const size_t orow = ((size_t)b * T_) * H_ + o0g;
    const bool ldx0 = (tid < KIN / 4);
    const int kcp = (4 * tid) / CH, koff = (4 * tid) % CH;

    for (int t = 0; t < T_; ++t) {
        const int cb = t & 1, nb = cb ^ 1;

        // prefetch x[t+1] (global, off-chain)
        float4 xl;
        const bool ldx = ldx0 && (t + 1 < T_);
        if (ldx) xl = __ldg((const float4*)(xin + ((size_t)b * T_ + t + 1) * KIN + 4 * tid));

        // ---- x-projection partials (off-chain; no dependence on peer data) ----
        ull aP0 = 0, aP1 = 0;                           // out pairs (o0,o0+1), (o0+2,o0+3)
        {
            const float* xb = &xstg[cb * 8 * XP + kc * XP];
            const float* wb = &Wx[kc * WC + o0];
#pragma unroll
            for (int k = 0; k < CH; ++k) {
                ull xs = splat2(xb[k]);
                ulonglong2 wv = *(const ulonglong2*)(wb + k * 132);
                fma2(aP0, xs, wv.x);
                fma2(aP1, xs, wv.y);
            }
        }

        if (t > 0)
            mbar_wait_cluster(my_mbar + (unsigned)nb * 8u, (unsigned)((t - 1) >> 1) & 1u);
        if (tid == 0) mbar_expect_tx(my_mbar + (unsigned)cb * 8u, 512u);

        // ---- h matvec: 4 outputs over 32-k chunk (8 LDS.128) ----
        const float* hb = &h_sm[cb * 288 + kc * 36];
        ull a0 = 0, a1 = 0, a2 = 0, a3 = 0;
#pragma unroll
        for (int j = 0; j < 8; ++j) {
            ulonglong2 hv = *(const ulonglong2*)(hb + j * 4);
            fma2(a0, hv.x, wq[0][2 * j]); fma2(a0, hv.y, wq[0][2 * j + 1]);
            fma2(a1, hv.x, wq[1][2 * j]); fma2(a1, hv.y, wq[1][2 * j + 1]);
            fma2(a2, hv.x, wq[2][2 * j]); fma2(a2, hv.y, wq[2][2 * j + 1]);
            fma2(a3, hv.x, wq[3][2 * j]); fma2(a3, hv.y, wq[3][2 * j + 1]);
        }
        float p0 = lo2(a0) + hi2(a0) + lo2(aP0);
        float p1 = lo2(a1) + hi2(a1) + hi2(aP0);
        float p2 = lo2(a2) + hi2(a2) + lo2(aP1);
        float p3 = lo2(a3) + hi2(a3) + hi2(aP1);

#pragma unroll
        for (int off = 4; off > 0; off >>= 1) {
            p0 += __shfl_down_sync(0xffffffffu, p0, off);
            p1 += __shfl_down_sync(0xffffffffu, p1, off);
            p2 += __shfl_down_sync(0xffffffffu, p2, off);
            p3 += __shfl_down_sync(0xffffffffu, p3, off);
        }

        if (epi) {
            float h0 = tanh_fast(bv.x + p0);
            float h1v = tanh_fast(bv.y + p1);
            float h2v = tanh_fast(bv.z + p2);
            float h3 = tanh_fast(bv.w + p3);
            *(float4*)&h_sm[nb * 288 + chunk * 36 + coff] = make_float4(h0, h1v, h2v, h3);
            unsigned paddr = peer_h + (unsigned)(nb * 288 + (chunk + 4) * 36 + coff) * 4u;
            st_async_b64(paddr,      pack2(h0, h1v), peer_mbar + (unsigned)cb * 8u);
            st_async_b64(paddr + 8u, pack2(h2v, h3), peer_mbar + (unsigned)cb * 8u);
            if (STORE_ALL)
                *(float4*)(hout + orow + (size_t)t * H_) = make_float4(h0, h1v, h2v, h3);
            else if (t == T_ - 1)
                *(float4*)(hout + (size_t)b * H_ + o0g) = make_float4(h0, h1v, h2v, h3);
        }
        if (ldx) *(float4*)&xstg[nb * 8 * XP + kcp * XP + koff] = xl;
        __syncthreads();
    }
    mbar_wait_cluster(my_mbar + (unsigned)((T_ - 1) & 1) * 8u,
                      (unsigned)((T_ - 1) >> 1) & 1u);
    cluster_sync_();
}

// =====================================================================================
// Final FC: out[b] = dot(h2last[b,:], W_fc[0,:]) + b_fc[0]
// =====================================================================================
__global__ void fc_kernel(const float* __restrict__ h2l, const float* __restrict__ Wfc,
                          const float* __restrict__ bfc, float* __restrict__ out)
{
    __shared__ float red[8];
    int b = blockIdx.x, tid = threadIdx.x;
    float v = h2l[(size_t)b * H_ + tid] * Wfc[tid];
#pragma unroll
    for (int o = 16; o > 0; o >>= 1) v += __shfl_down_sync(0xffffffffu, v, o);
    if ((tid & 31) == 0) red[tid >> 5] = v;
    __syncthreads();
    if (tid < 8) {
        float s = red[tid];
#pragma unroll
        for (int o = 4; o > 0; o >>= 1) s += __shfl_down_sync(0xffu, s, o);
        if (tid == 0) out[b] = s + bfc[0];
    }
}

// =====================================================================================
extern "C" void kernel_launch(void* const* d_in, const int* in_sizes, int n_in,
                              void* d_out, int out_size)
{
    const float* x     = (const float*)d_in[0];
    const float* W_ih0 = (const float*)d_in[1];
    const float* W_hh0 = (const float*)d_in[2];
    const float* b_ih0 = (const float*)d_in[3];
    const float* b_hh0 = (const float*)d_in[4];
    const float* W_ih1 = (const float*)d_in[5];
    const float* W_hh1 = (const float*)d_in[6];
    const float* b_ih1 = (const float*)d_in[7];
    const float* b_hh1 = (const float*)d_in[8];
    const float* W_fc  = (const float*)d_in[9];
    const float* b_fc  = (const float*)d_in[10];
    float* out = (float*)d_out;

    float *h1, *h2l;
    cudaGetSymbolAddress((void**)&h1,  g_h1);
    cudaGetSymbolAddress((void**)&h2l, g_h2last);

    // smem bytes: 4 + 576 + 2*8*XP + 8*WC floats
    const int sm0 = (4 + 576 + 2 * 8 * (IN_ / 8 + 4) + 8 * ((IN_ / 8) * 132 + 4)) * 4;
    const int sm1 = (4 + 576 + 2 * 8 * (H_ / 8 + 4) + 8 * ((H_ / 8) * 132 + 4)) * 4;
    cudaFuncSetAttribute(rnn_recF<IN_, true>,  cudaFuncAttributeMaxDynamicSharedMemorySize, sm0);
    cudaFuncSetAttribute(rnn_recF<H_, false>,  cudaFuncAttributeMaxDynamicSharedMemorySize, sm1);

    // Layer 0: xp folded in-kernel (reads x directly)
    rnn_recF<IN_, true><<<128, 256, sm0>>>(x, W_ih0, b_ih0, b_hh0, W_hh0, h1);
    // Layer 1: xp1 folded in-kernel (reads completed h1 from global)
    rnn_recF<H_, false><<<128, 256, sm1>>>(h1, W_ih1, b_ih1, b_hh1, W_hh1, h2l);
    // Final projection
    fc_kernel<<<B_, H_>>>(h2l, W_fc, b_fc, out);
}

// round 17
// speedup vs baseline: 1.3721x; 1.3721x over previous
#include <cuda_runtime.h>
#include <math.h>

#define B_  64
#define T_  2048
#define IN_ 128
#define H_  256
#define M_  (B_ * T_)

typedef unsigned long long ull;

// ---------------- scratch ----------------
__device__ float g_xp[(size_t)B_ * T_ * H_];    // reused for xp0 then xp1
__device__ float g_h1[(size_t)B_ * T_ * H_];    // layer-0 hidden states
__device__ float g_h2last[(size_t)B_ * H_];     // h2[:, T-1, :]

// ---------------- packed fp32x2 helpers ----------------
__device__ __forceinline__ void fma2(ull &d, ull a, ull b) {
    asm("fma.rn.f32x2 %0, %1, %2, %0;" : "+l"(d) : "l"(a), "l"(b));
}
__device__ __forceinline__ void add2(ull &d, ull a, ull b) {
    asm("add.rn.f32x2 %0, %1, %2;" : "=l"(d) : "l"(a), "l"(b));
}
__device__ __forceinline__ ull splat2(float x) {
    ull r; asm("mov.b64 %0, {%1, %1};" : "=l"(r) : "f"(x)); return r;
}
__device__ __forceinline__ float lo2(ull v) { return __uint_as_float((unsigned)(v & 0xffffffffULL)); }
__device__ __forceinline__ float hi2(ull v) { return __uint_as_float((unsigned)(v >> 32)); }

__device__ __forceinline__ float tanh_fast(float s) {
    s = fminf(fmaxf(s, -15.f), 15.f);
    float e; asm("ex2.approx.f32 %0, %1;" : "=f"(e) : "f"(s * 2.885390082f));
    float r; asm("rcp.approx.f32 %0, %1;" : "=f"(r) : "f"(e + 1.f));
    return fmaf(-2.f, r, 1.f);
}

// ---------------- cluster / mbarrier helpers (rec3-proven) ----------------
__device__ __forceinline__ unsigned su32(const void* p) {
    return (unsigned)__cvta_generic_to_shared(p);
}
__device__ __forceinline__ unsigned cta_rank() {
    unsigned r; asm("mov.u32 %0, %%cluster_ctarank;" : "=r"(r)); return r;
}
__device__ __forceinline__ unsigned mapa_u32(unsigned addr, unsigned rank) {
    unsigned r; asm("mapa.shared::cluster.u32 %0, %1, %2;" : "=r"(r) : "r"(addr), "r"(rank));
    return r;
}
__device__ __forceinline__ void mbar_init(unsigned addr, unsigned cnt) {
    asm volatile("mbarrier.init.shared.b64 [%0], %1;" :: "r"(addr), "r"(cnt) : "memory");
}
__device__ __forceinline__ void mbar_expect_tx(unsigned addr, unsigned bytes) {
    asm volatile("mbarrier.arrive.expect_tx.shared.b64 _, [%0], %1;" :: "r"(addr), "r"(bytes) : "memory");
}
__device__ __forceinline__ void mbar_wait_cluster(unsigned addr, unsigned parity) {
    asm volatile(
        "{\n\t.reg .pred P;\n\t"
        "WL_%=:\n\t"
        "mbarrier.try_wait.parity.acquire.cluster.shared::cta.b64 P, [%0], %1, 0x989680;\n\t"
        "@P bra.uni WD_%=;\n\t"
        "bra.uni WL_%=;\n\t"
        "WD_%=:\n\t}"
        :: "r"(addr), "r"(parity) : "memory");
}
__device__ __forceinline__ void st_async_f32(unsigned raddr, float v, unsigned rmbar) {
    asm volatile(
        "st.async.shared::cluster.mbarrier::complete_tx::bytes.b32 [%0], %1, [%2];"
        :: "r"(raddr), "r"(__float_as_uint(v)), "r"(rmbar) : "memory");
}
__device__ __forceinline__ void cluster_sync_() {
    asm volatile("barrier.cluster.arrive.aligned;" ::: "memory");
    asm volatile("barrier.cluster.wait.aligned;" ::: "memory");
}

// 128-k dot: 32 broadcast LDS.128 + 64 fma2
__device__ __forceinline__ float dot128(const float* hb, const ull* wq) {
    ull a0 = 0, a1 = 0, a2 = 0, a3 = 0;
#pragma unroll
    for (int kk = 0; kk < 32; kk += 2) {
        ulonglong2 v0 = *(const ulonglong2*)(hb + kk * 4);
        ulonglong2 v1 = *(const ulonglong2*)(hb + kk * 4 + 4);
        fma2(a0, v0.x, wq[2 * kk]);
        fma2(a1, v0.y, wq[2 * kk + 1]);
        fma2(a2, v1.x, wq[2 * kk + 2]);
        fma2(a3, v1.y, wq[2 * kk + 3]);
    }
    ull s01, s23, s;
    add2(s01, a0, a1); add2(s23, a2, a3); add2(s, s01, s23);
    return lo2(s) + hi2(s);
}

// =====================================================================================
// Phase A / C GEMM (proven): C = A @ W^T + bias0 + bias1
// =====================================================================================
__global__ __launch_bounds__(256, 2)
void gemm_bias_kernel(const float* __restrict__ A, const float* __restrict__ W,
                      const float* __restrict__ bias0, const float* __restrict__ bias1,
                      float* __restrict__ C, int K)
{
    __shared__ float a_sm[16][132];
    __shared__ float b_sm[16][132];
    const int tid = threadIdx.x;
    const int tx = tid & 15, ty = tid >> 4;
    const int mBase = blockIdx.x * 128, nBase = blockIdx.y * 128;

    ull acc[8][4];
#pragma unroll
    for (int i = 0; i < 8; i++)
#pragma unroll
        for (int j = 0; j < 4; j++) acc[i][j] = 0ULL;

    for (int kt = 0; kt < K; kt += 16) {
#pragma unroll
        for (int l = 0; l < 2; l++) {
            int idx = l * 256 + tid, row = idx >> 2, kq = idx & 3;
            float4 v = *(const float4*)(A + (size_t)(mBase + row) * K + kt + kq * 4);
            a_sm[kq * 4 + 0][row] = v.x; a_sm[kq * 4 + 1][row] = v.y;
            a_sm[kq * 4 + 2][row] = v.z; a_sm[kq * 4 + 3][row] = v.w;
        }
#pragma unroll
        for (int l = 0; l < 2; l++) {
            int idx = l * 256 + tid, row = idx >> 2, kq = idx & 3;
            float4 v = *(const float4*)(W + (size_t)(nBase + row) * K + kt + kq * 4);
            b_sm[kq * 4 + 0][row] = v.x; b_sm[kq * 4 + 1][row] = v.y;
            b_sm[kq * 4 + 2][row] = v.z; b_sm[kq * 4 + 3][row] = v.w;
        }
        __syncthreads();
#pragma unroll
        for (int kk = 0; kk < 16; kk++) {
            float4 a0 = *(const float4*)&a_sm[kk][ty * 8];
            float4 a1 = *(const float4*)&a_sm[kk][ty * 8 + 4];
            ulonglong2 b0 = *(const ulonglong2*)&b_sm[kk][tx * 8];
            ulonglong2 b1 = *(const ulonglong2*)&b_sm[kk][tx * 8 + 4];
            float av[8] = {a0.x, a0.y, a0.z, a0.w, a1.x, a1.y, a1.z, a1.w};
#pragma unroll
            for (int i = 0; i < 8; i++) {
                ull s = splat2(av[i]);
                fma2(acc[i][0], s, b0.x); fma2(acc[i][1], s, b0.y);
                fma2(acc[i][2], s, b1.x); fma2(acc[i][3], s, b1.y);
            }
        }
        __syncthreads();
    }
    const int n0 = nBase + tx * 8;
    float bj[8];
#pragma unroll
    for (int j = 0; j < 8; j++) bj[j] = bias0[n0 + j] + bias1[n0 + j];
#pragma unroll
    for (int i = 0; i < 8; i++) {
        int m = mBase + ty * 8 + i;
        float4 o0, o1;
        o0.x = lo2(acc[i][0]) + bj[0]; o0.y = hi2(acc[i][0]) + bj[1];
        o0.z = lo2(acc[i][1]) + bj[2]; o0.w = hi2(acc[i][1]) + bj[3];
        o1.x = lo2(acc[i][2]) + bj[4]; o1.y = hi2(acc[i][2]) + bj[5];
        o1.z = lo2(acc[i][3]) + bj[6]; o1.w = hi2(acc[i][3]) + bj[7];
        *(float4*)(C + (size_t)m * H_ + n0)     = o0;
        *(float4*)(C + (size_t)m * H_ + n0 + 4) = o1;
    }
}

// =====================================================================================
// Recurrence v9: rec3 EXACT data plan, but NO per-step __syncthreads.
// Epilogue lanes push BOTH copies of h via st.async: peer copy (offset 132+o on the
// peer, tx on peer mbar) AND self copy (offset o on self, tx on own mbar). Each
// phase's mbar expects 1024B = 512 self + 512 peer; the flip is therefore a full
// 2-CTA rendezvous: it implies every warp in both CTAs finished that step's sends,
// hence all reads of the buffer reused 2 steps later are complete. The loop has no
// generic smem writes at all, so no fences or BARs are needed.
// Slots/parity/drain identical to rec3: slot t&1, parity (t>>1)&1, wait slot
// (t-1)&1 at step t, final drain + cluster_sync.
// =====================================================================================
template<bool STORE_ALL>
__global__ void __cluster_dims__(2, 1, 1) __launch_bounds__(256, 1)
rnn_rec9(const float* __restrict__ xp, const float* __restrict__ Whh,
         float* __restrict__ hout)
{
    __shared__ __align__(16) float h_sm[2][264];   // [buf][own 0..128 | peer@132]
    __shared__ __align__(8)  ull mbar[2];

    const int tid = threadIdx.x;
    const unsigned rank = cta_rank();
    const unsigned peer = rank ^ 1u;
    const int b = blockIdx.x >> 1;
    const int w = tid >> 5, l = tid & 31;
    const int half = l & 1;                         // 0: own k-half, 1: peer k-half
    const int o = w * 16 + (l >> 1);                // local output 0..127
    const int o_glob = (int)rank * 128 + o;
    const int kh = half ? (int)peer : (int)rank;

    ull wq[64];
    {
        const ulonglong2* src = (const ulonglong2*)(Whh + (size_t)o_glob * H_ + kh * 128);
#pragma unroll
        for (int j = 0; j < 32; ++j) { ulonglong2 v = src[j]; wq[2 * j] = v.x; wq[2 * j + 1] = v.y; }
    }

    if (tid == 0) { mbar_init(su32(&mbar[0]), 1); mbar_init(su32(&mbar[1]), 1); }
    for (int i = tid; i < 2 * 264; i += 256) ((float*)h_sm)[i] = 0.f;   // h[-1] = 0
    __syncthreads();
    cluster_sync_();                                 // mbars + zeroed buffers visible

    const unsigned my_mbar   = su32(&mbar[0]);
    const unsigned peer_mbar = mapa_u32(my_mbar, peer);
    const unsigned self_h    = mapa_u32(su32(&h_sm[0][0]), rank);
    const unsigned peer_h    = mapa_u32(su32(&h_sm[0][0]), peer);
    const int hoff = half ? 132 : 0;

    const size_t xrow = ((size_t)b * T_) * H_ + o_glob;
    float xv = (half == 0) ? __ldg(xp + xrow) : 0.f;

    for (int t = 0; t < T_; ++t) {
        const int cb = t & 1, nb = cb ^ 1;

        // prefetch xp[t+1] (hidden under wait + matvec)
        float xvn = 0.f;
        if (half == 0 && t + 1 < T_) xvn = __ldg(xp + xrow + (size_t)(t + 1) * H_);

        if (t > 0)
            mbar_wait_cluster(my_mbar + (unsigned)nb * 8u,          // slot (t-1)&1
                              (unsigned)((t - 1) >> 1) & 1u);
        if (tid == 0) mbar_expect_tx(my_mbar + (unsigned)cb * 8u, 1024u);

        float p = dot128(&h_sm[cb][hoff], wq);
        float q = __shfl_down_sync(0xffffffffu, p, 1);

        if (half == 0) {
            float h = tanh_fast(xv + p + q);
            // self copy (own chunk, offset o) — tx counted on OWN mbar
            st_async_f32(self_h + (unsigned)(nb * 264 + o) * 4u,
                         h, my_mbar + (unsigned)cb * 8u);
            // peer copy (their peer-chunk, offset 132+o) — tx on PEER mbar
            st_async_f32(peer_h + (unsigned)(nb * 264 + 132 + o) * 4u,
                         h, peer_mbar + (unsigned)cb * 8u);
            if (STORE_ALL)
                hout[xrow + (size_t)t * H_] = h;
            else if (t == T_ - 1)
                hout[(size_t)b * H_ + o_glob] = h;
        }
        xv = xvn;
    }

    // drain final phase on both CTAs before exit
    mbar_wait_cluster(my_mbar + (unsigned)((T_ - 1) & 1) * 8u,
                      (unsigned)((T_ - 1) >> 1) & 1u);
    cluster_sync_();
}

// =====================================================================================
// Final FC
// =====================================================================================
__global__ void fc_kernel(const float* __restrict__ h2l, const float* __restrict__ Wfc,
                          const float* __restrict__ bfc, float* __restrict__ out)
{
    __shared__ float red[8];
    int b = blockIdx.x, tid = threadIdx.x;
    float v = h2l[(size_t)b * H_ + tid] * Wfc[tid];
#pragma unroll
    for (int o = 16; o > 0; o >>= 1) v += __shfl_down_sync(0xffffffffu, v, o);
    if ((tid & 31) == 0) red[tid >> 5] = v;
    __syncthreads();
    if (tid < 8) {
        float s = red[tid];
#pragma unroll
        for (int o = 4; o > 0; o >>= 1) s += __shfl_down_sync(0xffu, s, o);
        if (tid == 0) out[b] = s + bfc[0];
    }
}

// =====================================================================================
extern "C" void kernel_launch(void* const* d_in, const int* in_sizes, int n_in,
                              void* d_out, int out_size)
{
    const float* x     = (const float*)d_in[0];
    const float* W_ih0 = (const float*)d_in[1];
    const float* W_hh0 = (const float*)d_in[2];
    const float* b_ih0 = (const float*)d_in[3];
    const float* b_hh0 = (const float*)d_in[4];
    const float* W_ih1 = (const float*)d_in[5];
    const float* W_hh1 = (const float*)d_in[6];
    const float* b_ih1 = (const float*)d_in[7];
    const float* b_hh1 = (const float*)d_in[8];
    const float* W_fc  = (const float*)d_in[9];
    const float* b_fc  = (const float*)d_in[10];
    float* out = (float*)d_out;

    float *xp, *h1, *h2l;
    cudaGetSymbolAddress((void**)&xp,  g_xp);
    cudaGetSymbolAddress((void**)&h1,  g_h1);
    cudaGetSymbolAddress((void**)&h2l, g_h2last);

    dim3 ggemm(M_ / 128, H_ / 128);

    // Phase A: xp0 = x @ W_ih0^T + b_ih0 + b_hh0
    gemm_bias_kernel<<<ggemm, 256>>>(x, W_ih0, b_ih0, b_hh0, xp, IN_);
    // Phase B: layer-0 recurrence (barrier-free step)
    rnn_rec9<true><<<128, 256>>>(xp, W_hh0, h1);
    // Phase C: xp1 = h1 @ W_ih1^T + b_ih1 + b_hh1
    gemm_bias_kernel<<<ggemm, 256>>>(h1, W_ih1, b_ih1, b_hh1, xp, H_);
    // Phase D: layer-1 recurrence, writes only h2[T-1]
    rnn_rec9<false><<<128, 256>>>(xp, W_hh1, h2l);
    // Phase E: final projection
    fc_kernel<<<B_, H_>>>(h2l, W_fc, b_fc, out);
}